// round 4
// baseline (speedup 1.0000x reference)
#include <cuda_runtime.h>

// ---------------- problem constants ----------------
#define KCLS 20
#define HH   480
#define WW   640
#define NPIX (HH * WW)           // 307200
#define NBATCH 4
#define FC   512
#define FH   30
#define FW   40
#define FHW  (FH * FW)           // 1200
#define NBOX 5
#define COUNT_THRESH 10000
// x_cropped elements: (NB+1) * N * C * H * W
#define XELEMS ((long long)(NBOX + 1) * NBATCH * FC * FHW)   // 14,745,600

// ---------------- device scratch (no allocations allowed) ----------------
__device__ int g_cnt[KCLS];
__device__ int g_minx[KCLS], g_maxx[KCLS], g_miny[KCLS], g_maxy[KCLS];
// per node: x0, y0, crop_w, crop_h
__device__ int g_node[NBOX][4];

// ---------------- kernel 0: reset stats (graph replays must be deterministic) ----
__global__ void k_init() {
    int k = threadIdx.x;
    if (k < KCLS) {
        g_cnt[k]  = 0;
        g_minx[k] = WW;  g_maxx[k] = -1;
        g_miny[k] = HH;  g_maxy[k] = -1;
    }
}

// ---------------- kernel 1: argmax over K=20 for batch 3 + per-class stats ------
// One thread handles 4 consecutive pixels via float4 loads (coalesced per k-slice).
__global__ void k_stats(const float* __restrict__ seg) {
    __shared__ int s_cnt[KCLS], s_minx[KCLS], s_maxx[KCLS], s_miny[KCLS], s_maxy[KCLS];
    int t = threadIdx.x;
    if (t < KCLS) {
        s_cnt[t] = 0;
        s_minx[t] = WW;  s_maxx[t] = -1;
        s_miny[t] = HH;  s_maxy[t] = -1;
    }
    __syncthreads();

    int p4 = blockIdx.x * blockDim.x + t;           // quad-pixel index, [0, 76800)
    // batch 3 slice base
    const float4* base = (const float4*)(seg + (long long)3 * KCLS * NPIX);

    float b0 = -1e30f, b1 = -1e30f, b2 = -1e30f, b3 = -1e30f;
    int   k0 = 0, k1 = 0, k2 = 0, k3 = 0;
#pragma unroll
    for (int k = 0; k < KCLS; k++) {
        float4 v = __ldg(base + (long long)k * (NPIX / 4) + p4);
        if (v.x > b0) { b0 = v.x; k0 = k; }
        if (v.y > b1) { b1 = v.y; k1 = k; }
        if (v.z > b2) { b2 = v.z; k2 = k; }
        if (v.w > b3) { b3 = v.w; k3 = k; }
    }

    int y  = p4 / (WW / 4);                 // same row for all 4 pixels
    int xb = (p4 % (WW / 4)) * 4;

    // pixel 0
    atomicAdd(&s_cnt[k0], 1);
    atomicMin(&s_minx[k0], xb + 0); atomicMax(&s_maxx[k0], xb + 0);
    atomicMin(&s_miny[k0], y);      atomicMax(&s_maxy[k0], y);
    // pixel 1
    atomicAdd(&s_cnt[k1], 1);
    atomicMin(&s_minx[k1], xb + 1); atomicMax(&s_maxx[k1], xb + 1);
    atomicMin(&s_miny[k1], y);      atomicMax(&s_maxy[k1], y);
    // pixel 2
    atomicAdd(&s_cnt[k2], 1);
    atomicMin(&s_minx[k2], xb + 2); atomicMax(&s_maxx[k2], xb + 2);
    atomicMin(&s_miny[k2], y);      atomicMax(&s_maxy[k2], y);
    // pixel 3
    atomicAdd(&s_cnt[k3], 1);
    atomicMin(&s_minx[k3], xb + 3); atomicMax(&s_maxx[k3], xb + 3);
    atomicMin(&s_miny[k3], y);      atomicMax(&s_maxy[k3], y);

    __syncthreads();
    if (t < KCLS) {
        if (s_cnt[t] > 0) {
            atomicAdd(&g_cnt[t], s_cnt[t]);
            atomicMin(&g_minx[t], s_minx[t]); atomicMax(&g_maxx[t], s_maxx[t]);
            atomicMin(&g_miny[t], s_miny[t]); atomicMax(&g_maxy[t], s_maxy[t]);
        }
    }
}

// ---------------- kernel 2: selection logic + pool_x / scalar outputs -----------
__global__ void k_select(float* __restrict__ out, const float* __restrict__ pool,
                         int pool_n, int x_off) {
    int t = threadIdx.x;

    if (t == 0) {
        // present classes (ascending id), drop the first one (np.unique()[1:])
        int cand[KCLS], ccnt[KCLS];
        int m = 0, first_seen = -1;
        for (int k = 0; k < KCLS; k++) {
            if (g_cnt[k] > 0) {
                if (first_seen < 0) first_seen = k;
                else { cand[m] = k; ccnt[m] = g_cnt[k]; m++; }
            }
        }
        // stable selection by descending count (ties: lower id first)
        bool used[KCLS];
        for (int i = 0; i < m; i++) used[i] = false;
        int selb[NBOX - 2];
        int selcnt = 0;
        for (int r = 0; r < m && selcnt < NBOX - 2; r++) {
            int best = -1;
            for (int j = 0; j < m; j++)
                if (!used[j] && (best < 0 || ccnt[j] > ccnt[best])) best = j;
            used[best] = true;
            if (ccnt[best] > COUNT_THRESH) selb[selcnt++] = cand[best];
        }
        // build node boxes
        for (int i = 0; i < selcnt; i++) {
            int k  = selb[i];
            int x0 = g_minx[k] >> 4, y0 = g_miny[k] >> 4;
            int x1 = g_maxx[k] >> 4, y1 = g_maxy[k] >> 4;
            int cw = x1 - x0; if (cw < 1) cw = 1;
            int ch = y1 - y0; if (ch < 1) ch = 1;
            g_node[i][0] = x0; g_node[i][1] = y0;
            g_node[i][2] = cw; g_node[i][3] = ch;
        }
        const int bb[5][4] = {
            {FW / 4, FH / 4, 3 * FW / 4, 3 * FH / 4},
            {0, 0, FW / 3, FH},
            {0, 0, FW, FH / 3},
            {2 * FW / 3, 0, FW, FH},
            {0, 2 * FH / 3, FW, FH}};
        int need = NBOX - selcnt;
        for (int i = 0; i < need; i++) {
            int x0 = bb[i][0], y0 = bb[i][1];
            int cw = bb[i][2] - x0, ch = bb[i][3] - y0;
            g_node[selcnt + i][0] = x0; g_node[selcnt + i][1] = y0;
            g_node[selcnt + i][2] = cw; g_node[selcnt + i][3] = ch;
        }
        // scalar outputs NB, N (tuple items 2,3) if layout matches pool + 2 scalars
        if (x_off == pool_n + 2) {
            out[pool_n]     = (float)NBOX;     // 5
            out[pool_n + 1] = (float)NBATCH;   // 4
        }
    }

    // pool_x copy (tuple item 0)
    if (x_off >= pool_n) {
        for (int i = t; i < pool_n; i += blockDim.x) out[i] = pool[i];
    }
}

// ---------------- kernel 3: crop+bilinear-resize nodes, append feat -------------
// grid: (24, 512). o<20: plane-group o = n*5 + b of graph_nodes; o>=20: feat copy.
__global__ void k_build(float* __restrict__ out_x, const float* __restrict__ feat) {
    int o = blockIdx.x;        // 0..23
    int c = blockIdx.y;        // 0..511
    float* dst = out_x + ((long long)o * FC + c) * FHW;

    if (o >= 20) {             // straight feat append
        const float* src = feat + ((long long)(o - 20) * FC + c) * FHW;
        for (int i = threadIdx.x; i < FHW; i += blockDim.x) dst[i] = src[i];
        return;
    }

    int n = o / NBOX;
    int b = o % NBOX;

    __shared__ int   sx0[FW], sx1[FW], sy0[FH], sy1[FH];
    __shared__ float sfx[FW], sfy[FH];

    int x0 = g_node[b][0], y0 = g_node[b][1];
    int cw = g_node[b][2], ch = g_node[b][3];
    int t = threadIdx.x;

    if (t < FW) {   // half-pixel centers, clamp — jax bilinear (no antialias, scale>=1)
        float s = (t + 0.5f) * ((float)cw / (float)FW) - 0.5f;
        s = fminf(fmaxf(s, 0.0f), (float)(cw - 1));
        int i0 = (int)s;
        float f = s - (float)i0;
        int i1 = min(i0 + 1, cw - 1);
        sx0[t] = i0; sx1[t] = i1; sfx[t] = f;
    }
    if (t < FH) {
        float s = (t + 0.5f) * ((float)ch / (float)FH) - 0.5f;
        s = fminf(fmaxf(s, 0.0f), (float)(ch - 1));
        int i0 = (int)s;
        float f = s - (float)i0;
        int i1 = min(i0 + 1, ch - 1);
        sy0[t] = i0; sy1[t] = i1; sfy[t] = f;
    }
    __syncthreads();

    const float* src = feat + ((long long)n * FC + c) * FHW + y0 * FW + x0;

    for (int i = t; i < FHW; i += blockDim.x) {
        int h = i / FW;
        int w = i - h * FW;
        int   xa = sx0[w], xb = sx1[w];
        float fx = sfx[w];
        int   ya = sy0[h], yb = sy1[h];
        float fy = sfy[h];
        const float* r0 = src + ya * FW;
        const float* r1 = src + yb * FW;
        float v0 = (1.0f - fx) * __ldg(r0 + xa) + fx * __ldg(r0 + xb);
        float v1 = (1.0f - fx) * __ldg(r1 + xa) + fx * __ldg(r1 + xb);
        dst[i] = (1.0f - fy) * v0 + fy * v1;
    }
}

// ---------------- launcher ----------------
extern "C" void kernel_launch(void* const* d_in, const int* in_sizes, int n_in,
                              void* d_out, int out_size) {
    const float* seg  = (const float*)d_in[0];
    const float* feat = (const float*)d_in[1];
    const float* pool = (const float*)d_in[2];
    float* out = (float*)d_out;

    long long x_off_ll = (long long)out_size - XELEMS;
    if (x_off_ll < 0) x_off_ll = 0;
    int x_off = (int)x_off_ll;
    int pool_n = (n_in > 2) ? in_sizes[2] : 0;
    if (pool_n > x_off) pool_n = x_off;

    k_init<<<1, 32>>>();
    k_stats<<<NPIX / 4 / 256, 256>>>(seg);                    // 300 blocks
    k_select<<<1, 256>>>(out, pool, pool_n, x_off);
    dim3 grid((NBOX + 1) * NBATCH, FC);                       // (24, 512)
    k_build<<<grid, 256>>>(out + x_off, feat);
}

// round 5
// speedup vs baseline: 1.4796x; 1.4796x over previous
#include <cuda_runtime.h>

// ---------------- problem constants ----------------
#define KCLS 20
#define HH   480
#define WW   640
#define NPIX (HH * WW)           // 307200
#define NBATCH 4
#define FC   512
#define FH   30
#define FW   40
#define FHW  (FH * FW)           // 1200
#define NBOX 5
#define COUNT_THRESH 10000
#define XELEMS ((long long)(NBOX + 1) * NBATCH * FC * FHW)   // 14,745,600

// ---------------- device scratch ----------------
__device__ int g_cnt[KCLS];
__device__ int g_minx[KCLS], g_maxx[KCLS], g_miny[KCLS], g_maxy[KCLS];
__device__ int g_node[NBOX][4];   // x0, y0, cw, ch

// ---------------- kernel 0: reset stats ----------------
__global__ void k_init() {
    int k = threadIdx.x;
    if (k < KCLS) {
        g_cnt[k]  = 0;
        g_minx[k] = WW;  g_maxx[k] = -1;
        g_miny[k] = HH;  g_maxy[k] = -1;
    }
}

// ---------------- kernel 1: argmax(K=20) of batch 3 + per-class stats ----------
__global__ void k_stats(const float* __restrict__ seg) {
    __shared__ int s_cnt[KCLS], s_minx[KCLS], s_maxx[KCLS], s_miny[KCLS], s_maxy[KCLS];
    int t = threadIdx.x;
    if (t < KCLS) {
        s_cnt[t] = 0;
        s_minx[t] = WW;  s_maxx[t] = -1;
        s_miny[t] = HH;  s_maxy[t] = -1;
    }
    __syncthreads();

    int p4 = blockIdx.x * blockDim.x + t;           // quad-pixel index
    const float4* base = (const float4*)(seg + (long long)3 * KCLS * NPIX);

    float b0 = -1e30f, b1 = -1e30f, b2 = -1e30f, b3 = -1e30f;
    int   k0 = 0, k1 = 0, k2 = 0, k3 = 0;
#pragma unroll
    for (int k = 0; k < KCLS; k++) {
        float4 v = __ldg(base + k * (NPIX / 4) + p4);
        if (v.x > b0) { b0 = v.x; k0 = k; }
        if (v.y > b1) { b1 = v.y; k1 = k; }
        if (v.z > b2) { b2 = v.z; k2 = k; }
        if (v.w > b3) { b3 = v.w; k3 = k; }
    }

    int y  = p4 / (WW / 4);
    int xb = (p4 % (WW / 4)) * 4;

    atomicAdd(&s_cnt[k0], 1);
    atomicMin(&s_minx[k0], xb + 0); atomicMax(&s_maxx[k0], xb + 0);
    atomicMin(&s_miny[k0], y);      atomicMax(&s_maxy[k0], y);
    atomicAdd(&s_cnt[k1], 1);
    atomicMin(&s_minx[k1], xb + 1); atomicMax(&s_maxx[k1], xb + 1);
    atomicMin(&s_miny[k1], y);      atomicMax(&s_maxy[k1], y);
    atomicAdd(&s_cnt[k2], 1);
    atomicMin(&s_minx[k2], xb + 2); atomicMax(&s_maxx[k2], xb + 2);
    atomicMin(&s_miny[k2], y);      atomicMax(&s_maxy[k2], y);
    atomicAdd(&s_cnt[k3], 1);
    atomicMin(&s_minx[k3], xb + 3); atomicMax(&s_maxx[k3], xb + 3);
    atomicMin(&s_miny[k3], y);      atomicMax(&s_maxy[k3], y);

    __syncthreads();
    if (t < KCLS && s_cnt[t] > 0) {
        atomicAdd(&g_cnt[t], s_cnt[t]);
        atomicMin(&g_minx[t], s_minx[t]); atomicMax(&g_maxx[t], s_maxx[t]);
        atomicMin(&g_miny[t], s_miny[t]); atomicMax(&g_maxy[t], s_maxy[t]);
    }
}

// ---------------- kernel 2: selection + pool_x / scalar outputs ----------------
__global__ void k_select(float* __restrict__ out, const float* __restrict__ pool,
                         int pool_n, int x_off) {
    int t = threadIdx.x;

    if (t == 0) {
        int cand[KCLS], ccnt[KCLS];
        int m = 0, first_seen = -1;
        for (int k = 0; k < KCLS; k++) {
            if (g_cnt[k] > 0) {
                if (first_seen < 0) first_seen = k;
                else { cand[m] = k; ccnt[m] = g_cnt[k]; m++; }
            }
        }
        bool used[KCLS];
        for (int i = 0; i < m; i++) used[i] = false;
        int selb[NBOX - 2];
        int selcnt = 0;
        for (int r = 0; r < m && selcnt < NBOX - 2; r++) {
            int best = -1;
            for (int j = 0; j < m; j++)
                if (!used[j] && (best < 0 || ccnt[j] > ccnt[best])) best = j;
            used[best] = true;
            if (ccnt[best] > COUNT_THRESH) selb[selcnt++] = cand[best];
        }
        for (int i = 0; i < selcnt; i++) {
            int k  = selb[i];
            int x0 = g_minx[k] >> 4, y0 = g_miny[k] >> 4;
            int x1 = g_maxx[k] >> 4, y1 = g_maxy[k] >> 4;
            int cw = x1 - x0; if (cw < 1) cw = 1;
            int ch = y1 - y0; if (ch < 1) ch = 1;
            g_node[i][0] = x0; g_node[i][1] = y0;
            g_node[i][2] = cw; g_node[i][3] = ch;
        }
        const int bb[5][4] = {
            {FW / 4, FH / 4, 3 * FW / 4, 3 * FH / 4},
            {0, 0, FW / 3, FH},
            {0, 0, FW, FH / 3},
            {2 * FW / 3, 0, FW, FH},
            {0, 2 * FH / 3, FW, FH}};
        int need = NBOX - selcnt;
        for (int i = 0; i < need; i++) {
            int x0 = bb[i][0], y0 = bb[i][1];
            int cw = bb[i][2] - x0, ch = bb[i][3] - y0;
            g_node[selcnt + i][0] = x0; g_node[selcnt + i][1] = y0;
            g_node[selcnt + i][2] = cw; g_node[selcnt + i][3] = ch;
        }
        if (x_off == pool_n + 2) {
            out[pool_n]     = (float)NBOX;
            out[pool_n + 1] = (float)NBATCH;
        }
    }

    if (x_off >= pool_n) {
        for (int i = t; i < pool_n; i += blockDim.x) out[i] = pool[i];
    }
}

// ---------------- kernel 3: crop + bilinear resize, append feat ----------------
// grid (24, 128), block (20, 15). Each block handles 4 channels of one plane o.
// o = n*5 + b for o<20 (graph_nodes, raw-reshape order); o>=20 -> feat copy.
// Output region is 8B-aligned (x_off=2050 floats) -> float2 vector ops.
__global__ __launch_bounds__(300) void k_build(float* __restrict__ out_x,
                                               const float* __restrict__ feat) {
    int o  = blockIdx.x;          // 0..23
    int c0 = blockIdx.y << 2;     // channel group base
    int tx = threadIdx.x;         // 0..19  (w pair index)
    int ty = threadIdx.y;         // 0..14  (h, and h+15)

    if (o >= 20) {                // straight feat append, 4 planes of float2
        int n   = o - 20;
        int tid = ty * 20 + tx;   // 0..299
        const float2* src = (const float2*)feat + ((n * FC + c0) * FHW >> 1);
        float2*       dst = (float2*)out_x + ((o * FC + c0) * FHW >> 1);
#pragma unroll
        for (int i = 0; i < 8; i++)                 // 4ch * 600 float2 = 2400
            dst[tid + i * 300] = __ldg(src + tid + i * 300);
        return;
    }

    int n = o / NBOX;
    int b = o - n * NBOX;

    int x0 = g_node[b][0], y0 = g_node[b][1];
    int cw = g_node[b][2], ch = g_node[b][3];
    float sxs = (float)cw / (float)FW;
    float sys = (float)ch / (float)FH;

    // x-lerp params for w = 2*tx and 2*tx+1 (registers, no shared)
    int xa0, xb0, xa1, xb1; float fx0, fx1;
    {
        float s = ((float)(2 * tx) + 0.5f) * sxs - 0.5f;
        s = fminf(fmaxf(s, 0.0f), (float)(cw - 1));
        xa0 = (int)s; fx0 = s - (float)xa0; xb0 = min(xa0 + 1, cw - 1);
        s = ((float)(2 * tx + 1) + 0.5f) * sxs - 0.5f;
        s = fminf(fmaxf(s, 0.0f), (float)(cw - 1));
        xa1 = (int)s; fx1 = s - (float)xa1; xb1 = min(xa1 + 1, cw - 1);
    }
    // y-lerp params for h = ty and ty+15 (row offsets premultiplied)
    int ry0[2], ry1[2]; float fyv[2];
#pragma unroll
    for (int hh = 0; hh < 2; hh++) {
        float s = ((float)(ty + hh * 15) + 0.5f) * sys - 0.5f;
        s = fminf(fmaxf(s, 0.0f), (float)(ch - 1));
        int ya = (int)s;
        fyv[hh] = s - (float)ya;
        ry0[hh] = ya * FW;
        ry1[hh] = min(ya + 1, ch - 1) * FW;
    }

    int src_base = (n * FC + c0) * FHW + y0 * FW + x0;
    int dst_base = (o * FC + c0) * FHW;

#pragma unroll
    for (int cc = 0; cc < 4; cc++) {
        const float* src = feat + src_base + cc * FHW;
        float*       dst = out_x + dst_base + cc * FHW;
#pragma unroll
        for (int hh = 0; hh < 2; hh++) {
            const float* r0 = src + ry0[hh];
            const float* r1 = src + ry1[hh];
            float fy  = fyv[hh];
            float ofy = 1.0f - fy;
            float t0 = (1.0f - fx0) * __ldg(r0 + xa0) + fx0 * __ldg(r0 + xb0);
            float u0 = (1.0f - fx0) * __ldg(r1 + xa0) + fx0 * __ldg(r1 + xb0);
            float t1 = (1.0f - fx1) * __ldg(r0 + xa1) + fx1 * __ldg(r0 + xb1);
            float u1 = (1.0f - fx1) * __ldg(r1 + xa1) + fx1 * __ldg(r1 + xb1);
            float2 pv;
            pv.x = ofy * t0 + fy * u0;
            pv.y = ofy * t1 + fy * u1;
            ((float2*)(dst + (ty + hh * 15) * FW))[tx] = pv;
        }
    }
}

// ---------------- launcher ----------------
extern "C" void kernel_launch(void* const* d_in, const int* in_sizes, int n_in,
                              void* d_out, int out_size) {
    const float* seg  = (const float*)d_in[0];
    const float* feat = (const float*)d_in[1];
    const float* pool = (const float*)d_in[2];
    float* out = (float*)d_out;

    long long x_off_ll = (long long)out_size - XELEMS;
    if (x_off_ll < 0) x_off_ll = 0;
    int x_off = (int)x_off_ll;
    int pool_n = (n_in > 2) ? in_sizes[2] : 0;
    if (pool_n > x_off) pool_n = x_off;

    k_init<<<1, 32>>>();
    k_stats<<<NPIX / 4 / 256, 256>>>(seg);
    k_select<<<1, 256>>>(out, pool, pool_n, x_off);
    dim3 grid((NBOX + 1) * NBATCH, FC / 4);     // (24, 128)
    dim3 blk(20, 15);                           // 300 threads
    k_build<<<grid, blk>>>(out + x_off, feat);
}